// round 17
// baseline (speedup 1.0000x reference)
#include <cuda_runtime.h>
#include <cuda_fp16.h>
#include <cstdint>

#define NN 100000
#define NE 1600000
#define DF 128
#define DH 64
#define SLOT 64      // per-node edge bucket; P(indeg>64)~0 for Poisson(16)

// ---------------- device scratch ----------------
__device__ unsigned       g_pack[NN];          // bits 24-31: count, 0-23: w*2^17
__device__ float          g_deg[NN];           // d^{-1/2}
__device__ unsigned       g_cnt[NN];           // padded in-degree (mult of 8)
__device__ int2           g_edge[(size_t)NN * SLOT];  // (row*128, w as half2 bits)
__device__ __half2        g_h1[NN * (DH/2)];   // dinv-scaled x@W1 (after prep)
__device__ float          g_h2[NN];            // d * (relu(layer1).W2)

__device__ __forceinline__ __half2 u2h2(unsigned u) {
    return *reinterpret_cast<__half2*>(&u);
}

// ---------------- K1: 32-bit packed degree atomic + direct bucket write -----
// Record: (row byte-offset into g_h1, weight as duplicated half2 bits).
__global__ void k_deg(const int* __restrict__ rows, const int* __restrict__ cols,
                      const float* __restrict__ ew) {
    int e = blockIdx.x * blockDim.x + threadIdx.x;
    if (e >= NE) return;
    int c = cols[e];
    float w = ew[e];
    unsigned v = (1u << 24) | (unsigned)(w * 131072.0f + 0.5f);
    unsigned old = atomicAdd(&g_pack[c], v);
    unsigned rank = old >> 24;
    if (rank < SLOT) {
        __half2 wh = __float2half2_rn(w);
        g_edge[(size_t)c * SLOT + rank] =
            make_int2(rows[e] << 7, *reinterpret_cast<int*>(&wh));
    }
}

// ---------------- K2 (prep): dinv + scale h1 + pad buckets + reset ----------
// One warp handles 2 nodes: lanes 0-15 node 2w, lanes 16-31 node 2w+1.
__global__ void __launch_bounds__(256) k_prep() {
    int gw  = (blockIdx.x * blockDim.x + threadIdx.x) >> 5;
    int lane = threadIdx.x & 31;
    int n = gw * 2 + (lane >> 4);
    if (n >= NN) return;
    int q = lane & 15;

    unsigned pk = g_pack[n];                    // broadcast within 16 lanes
    float dsum = (float)(pk & 0xFFFFFFu) * (1.0f / 131072.0f);
    float d = rsqrtf(1.0f + dsum);              // +1 = self loop

    uint2* h1 = reinterpret_cast<uint2*>(g_h1);
    uint2 v = h1[(size_t)n * 16 + q];
    float2 f0 = __half22float2(u2h2(v.x));
    float2 f1 = __half22float2(u2h2(v.y));
    __half2 o0 = __floats2half2_rn(f0.x * d, f0.y * d);
    __half2 o1 = __floats2half2_rn(f1.x * d, f1.y * d);
    v.x = *reinterpret_cast<unsigned*>(&o0);
    v.y = *reinterpret_cast<unsigned*>(&o1);
    h1[(size_t)n * 16 + q] = v;

    unsigned cnt = pk >> 24;
    cnt = min(cnt, (unsigned)SLOT);
    unsigned pad = (8u - (cnt & 7u)) & 7u;      // pad to multiple of 8 (<=64)
    if ((unsigned)q < pad)                      // dummy: row-offset 0, w = 0
        g_edge[(size_t)n * SLOT + cnt + q] = make_int2(0, 0);

    if (q == 0) {
        g_deg[n]  = d;
        g_cnt[n]  = cnt + pad;                  // padded count
        g_pack[n] = 0u;                         // restore for next replay
    }
}

// ---------------- K3: h1 = x @ W1, fp32 accum (f32x2) -> fp16 store ---------
__global__ void __launch_bounds__(128) k_gemm1(const float* __restrict__ x,
                                               const float* __restrict__ W1) {
    __shared__ unsigned long long Ws[DF * (DH / 2)];  // 32KB
    int tid = threadIdx.x;
    const unsigned long long* W64 = reinterpret_cast<const unsigned long long*>(W1);
    for (int i = tid; i < DF * (DH / 2); i += 128) Ws[i] = W64[i];
    __syncthreads();

    int row = blockIdx.x * 128 + tid;
    if (row >= NN) return;

    unsigned long long acc[DH / 2];
    #pragma unroll
    for (int j = 0; j < DH / 2; j++) acc[j] = 0ULL;

    const float4* xr = reinterpret_cast<const float4*>(x + (size_t)row * DF);
    #pragma unroll 1
    for (int k4 = 0; k4 < DF / 4; k4++) {
        float4 xv = __ldg(&xr[k4]);
        float xs4[4] = {xv.x, xv.y, xv.z, xv.w};
        #pragma unroll
        for (int kk = 0; kk < 4; kk++) {
            unsigned long long xp;
            unsigned xb = __float_as_uint(xs4[kk]);
            asm("mov.b64 %0, {%1, %1};" : "=l"(xp) : "r"(xb));
            const unsigned long long* wr = &Ws[(k4 * 4 + kk) * (DH / 2)];
            #pragma unroll
            for (int j = 0; j < DH / 2; j++) {
                asm("fma.rn.f32x2 %0, %1, %2, %0;" : "+l"(acc[j]) : "l"(xp), "l"(wr[j]));
            }
        }
    }
    uint4* hr = reinterpret_cast<uint4*>(&g_h1[(size_t)row * (DH / 2)]);
    #pragma unroll
    for (int q = 0; q < 8; q++) {
        unsigned p[4];
        #pragma unroll
        for (int k = 0; k < 4; k++) {
            unsigned lo, hi;
            asm("mov.b64 {%0, %1}, %2;" : "=r"(lo), "=r"(hi) : "l"(acc[q * 4 + k]));
            __half2 h = __floats2half2_rn(__uint_as_float(lo), __uint_as_float(hi));
            p[k] = *reinterpret_cast<unsigned*>(&h);
        }
        hr[q] = make_uint4(p[0], p[1], p[2], p[3]);
    }
}

// ---------------- K4: gather layer-1 -> h2s --------------------------------
// One warp per node, two 16-lane halves. Each half does 4 consecutive edges
// per outer iter via two LDG.128 record-pair loads; per edge: no cvt, no
// predicate, 1/2 LDG.128 + 1 LDG.64 + 2 HFMA2. fp16 partials flushed to fp32
// every 4 edges.
__global__ void __launch_bounds__(256) k_gather1(const float* __restrict__ b1,
                                                 const float* __restrict__ W2) {
    int warp = (blockIdx.x * blockDim.x + threadIdx.x) >> 5;
    int lane = threadIdx.x & 31;
    if (warp >= NN) return;

    unsigned cnt = g_cnt[warp];
    const uint4* eb4 = reinterpret_cast<const uint4*>(&g_edge[(size_t)warp * SLOT]);
    int half = lane >> 4;
    int q    = lane & 15;                       // features 4q..4q+3
    const char* h1b = reinterpret_cast<const char*>(g_h1);
    unsigned qoff = (unsigned)q * 8u;

    float a0 = 0.f, a1 = 0.f, a2 = 0.f, a3 = 0.f;
    for (unsigned e = 0; e < cnt; e += 8) {     // half0: e..e+3, half1: e+4..e+7
        unsigned pb = (e >> 1) + (unsigned)(half << 1);
        uint4 r01 = eb4[pb];                    // records 2k, 2k+1
        uint4 r23 = eb4[pb + 1];                // records 2k+2, 2k+3
        __half2 p0 = u2h2(0u), p1 = u2h2(0u);

        uint2 h;
        h = *reinterpret_cast<const uint2*>(h1b + (unsigned)r01.x + qoff);
        p0 = __hfma2(u2h2(r01.y), u2h2(h.x), p0);
        p1 = __hfma2(u2h2(r01.y), u2h2(h.y), p1);
        h = *reinterpret_cast<const uint2*>(h1b + (unsigned)r01.z + qoff);
        p0 = __hfma2(u2h2(r01.w), u2h2(h.x), p0);
        p1 = __hfma2(u2h2(r01.w), u2h2(h.y), p1);
        h = *reinterpret_cast<const uint2*>(h1b + (unsigned)r23.x + qoff);
        p0 = __hfma2(u2h2(r23.y), u2h2(h.x), p0);
        p1 = __hfma2(u2h2(r23.y), u2h2(h.y), p1);
        h = *reinterpret_cast<const uint2*>(h1b + (unsigned)r23.z + qoff);
        p0 = __hfma2(u2h2(r23.w), u2h2(h.x), p0);
        p1 = __hfma2(u2h2(r23.w), u2h2(h.y), p1);

        float2 f0 = __half22float2(p0);
        float2 f1 = __half22float2(p1);
        a0 += f0.x; a1 += f0.y; a2 += f1.x; a3 += f1.y;
    }
    a0 += __shfl_down_sync(0xffffffffu, a0, 16);
    a1 += __shfl_down_sync(0xffffffffu, a1, 16);
    a2 += __shfl_down_sync(0xffffffffu, a2, 16);
    a3 += __shfl_down_sync(0xffffffffu, a3, 16);

    // lanes 0..15: self term + column scaling
    float d = g_deg[warp];
    uint2 hv = *reinterpret_cast<const uint2*>(
        h1b + ((unsigned)warp << 7) + qoff);
    float2 fa = __half22float2(u2h2(hv.x));
    float2 fb = __half22float2(u2h2(hv.y));
    a0 = d * (a0 + fa.x);
    a1 = d * (a1 + fa.y);
    a2 = d * (a2 + fb.x);
    a3 = d * (a3 + fb.y);

    float4 bb = reinterpret_cast<const float4*>(b1)[q];
    float4 ww = reinterpret_cast<const float4*>(W2)[q];
    float s = fmaxf(a0 + bb.x, 0.f) * ww.x
            + fmaxf(a1 + bb.y, 0.f) * ww.y
            + fmaxf(a2 + bb.z, 0.f) * ww.z
            + fmaxf(a3 + bb.w, 0.f) * ww.w;
    #pragma unroll
    for (int off = 8; off > 0; off >>= 1)
        s += __shfl_xor_sync(0xffffffffu, s, off);
    if (lane == 0) g_h2[warp] = d * s;          // h2s = d * h2_raw
}

// ---------------- K5: gather layer-2 -> out (loop-free) ----------------
// cnt <= 64 = 32 lanes x 2 records: one predicated uint4 load per lane.
// out[c] = d_c*(sum_e w_e*h2s[r] + h2s[c]) + b2 ; dummies add 0.
__global__ void __launch_bounds__(256) k_gather2(float* __restrict__ out,
                                                 const float* __restrict__ b2) {
    int warp = (blockIdx.x * blockDim.x + threadIdx.x) >> 5;
    int lane = threadIdx.x & 31;
    if (warp >= NN) return;
    unsigned cnt = g_cnt[warp];
    const uint4* eb4 = reinterpret_cast<const uint4*>(&g_edge[(size_t)warp * SLOT]);
    float acc = 0.f;
    if ((unsigned)(lane * 2) < cnt) {           // cnt is even (mult of 8)
        uint4 r = eb4[lane];
        float w0 = __low2float(u2h2(r.y));
        float w1 = __low2float(u2h2(r.w));
        acc = fmaf(w0, g_h2[(unsigned)r.x >> 7], acc);
        acc = fmaf(w1, g_h2[(unsigned)r.z >> 7], acc);
    }
    #pragma unroll
    for (int off = 16; off > 0; off >>= 1)
        acc += __shfl_xor_sync(0xffffffffu, acc, off);
    if (lane == 0) {
        float d = g_deg[warp];
        out[warp] = d * (acc + g_h2[warp]) + __ldg(&b2[0]);
    }
}

// ---------------- launch ----------------
extern "C" void kernel_launch(void* const* d_in, const int* in_sizes, int n_in,
                              void* d_out, int out_size) {
    const float* x  = (const float*)d_in[0];
    const int*   ei = (const int*)  d_in[1];
    const float* ew = (const float*)d_in[2];
    const float* W1 = (const float*)d_in[3];
    const float* b1 = (const float*)d_in[4];
    const float* W2 = (const float*)d_in[5];
    const float* b2 = (const float*)d_in[6];
    float* out = (float*)d_out;

    const int* rows = ei;        // sources (gather)
    const int* cols = ei + NE;   // targets (bucket key)

    static cudaStream_t s2 = nullptr;
    static cudaEvent_t evFork = nullptr, evJoin = nullptr;
    if (s2 == nullptr) {
        cudaStreamCreateWithFlags(&s2, cudaStreamNonBlocking);
        cudaEventCreateWithFlags(&evFork, cudaEventDisableTiming);
        cudaEventCreateWithFlags(&evJoin, cudaEventDisableTiming);
    }

    // Fork: GEMM1 (FMA-bound) overlaps the bucket build (LTS/atomic-bound).
    cudaEventRecord(evFork, 0);
    cudaStreamWaitEvent(s2, evFork, 0);
    k_gemm1<<<(NN + 127) / 128, 128, 0, s2>>>(x, W1);       // launch #1
    cudaEventRecord(evJoin, s2);

    k_deg<<<(NE + 255) / 256, 256>>>(rows, cols, ew);        // launch #2

    // prep needs BOTH deg (pack) and gemm1 (h1)
    cudaStreamWaitEvent(0, evJoin, 0);
    k_prep<<<(NN / 2 * 32 + 255) / 256, 256>>>();            // launch #3
    k_gather1<<<(NN * 32 + 255) / 256, 256>>>(b1, W2);       // launch #4 (profiled)
    k_gather2<<<(NN * 32 + 255) / 256, 256>>>(out, b2);      // launch #5
}